// round 8
// baseline (speedup 1.0000x reference)
#include <cuda_runtime.h>
#include <cuda_bf16.h>
#include <math.h>
#include <cstdint>

// ---------------- problem constants ----------------
#define BQ 2
#define LSEQ 4096
#define DMODEL 1024
#define DINNER 2048
#define NH 32
#define HD 64
#define DSTATE 128
#define CHK 64
#define NC 64
#define DPROJ 4384
#define CONVCH 2304
#define MROWS (BQ*LSEQ)

// int8 GEMM geometry
#define MT_A 512          // MROWS/16 row atoms
#define KT1 32            // GEMM1: K=1024 -> 32 k-atoms of 32
#define KT2 64            // GEMM2: K=2048
#define NPT1 280          // GEMM1: N=4384 padded 4480 -> 280 n-pairs of 16
#define NPT2 64           // GEMM2: N=1024

// ---------------- scratch (device globals; no allocation) ----------------
__device__ float g_zx[(size_t)MROWS * DPROJ];
__device__ float g_xbc[(size_t)MROWS * CONVCH];
__device__ float g_dt[MROWS * NH];
__device__ float g_acum[BQ * NC * NH * CHK];
__device__ float g_suma[BQ * NC * NH];
__device__ float g_states[(size_t)BQ * NC * NH * HD * DSTATE];
__device__ float g_y[(size_t)MROWS * DINNER];
__device__ unsigned g_amax[4];   // 0:u 1:W_in 2:W_out 3:y (zero-init; monotone, deterministic)

// packed int8 operand buffers: [limb][atoms][32 lanes][frag bytes]
__device__ __align__(128) int8_t g_qa1[2ull * MT_A * KT1 * 512];
__device__ __align__(128) int8_t g_qb1[2ull * NPT1 * KT1 * 512];
__device__ __align__(128) int8_t g_qa2[2ull * MT_A * KT2 * 512];
__device__ __align__(128) int8_t g_qb2[2ull * NPT2 * KT2 * 512];

// ---------------- PTX helpers ----------------
__device__ __forceinline__ uint32_t smem_u32(const void* p) {
    uint32_t a;
    asm("{ .reg .u64 t; cvta.to.shared.u64 t, %1; cvt.u32.u64 %0, t; }" : "=r"(a) : "l"(p));
    return a;
}
#define CP_ASYNC16(dst, src) \
    asm volatile("cp.async.cg.shared.global [%0], [%1], 16;" :: "r"(dst), "l"(src) : "memory")
#define CP_COMMIT() asm volatile("cp.async.commit_group;" ::: "memory")
#define CP_WAIT0()  asm volatile("cp.async.wait_group 0;" ::: "memory")
#define CP_WAIT1()  asm volatile("cp.async.wait_group 1;" ::: "memory")

__device__ __forceinline__ uint4 lds128(uint32_t addr) {
    uint4 v;
    asm volatile("ld.shared.v4.u32 {%0,%1,%2,%3}, [%4];"
                 : "=r"(v.x), "=r"(v.y), "=r"(v.z), "=r"(v.w) : "r"(addr));
    return v;
}

#define IMMA16832(d, a, b0, b1) \
    asm volatile("mma.sync.aligned.m16n8k32.row.col.s32.s8.s8.s32 " \
        "{%0,%1,%2,%3}, {%4,%5,%6,%7}, {%8,%9}, {%0,%1,%2,%3};" \
        : "+r"((d)[0]), "+r"((d)[1]), "+r"((d)[2]), "+r"((d)[3]) \
        : "r"((a).x), "r"((a).y), "r"((a).z), "r"((a).w), "r"(b0), "r"(b1))

// packed f32x2 (2x fp32 FMA rate) for SSD kernels
#define FMA2(d, a, b) asm("fma.rn.f32x2 %0, %1, %2, %0;" : "+l"(d) : "l"(a), "l"(b))
#define MUL2(d, a, b) asm("mul.rn.f32x2 %0, %1, %2;" : "=l"(d) : "l"(a), "l"(b))
__device__ __forceinline__ uint64_t dup2(float x) {
    uint64_t r; asm("mov.b64 %0, {%1, %1};" : "=l"(r) : "f"(x)); return r;
}
__device__ __forceinline__ void up2(uint64_t v, float& lo, float& hi) {
    asm("mov.b64 {%0, %1}, %2;" : "=f"(lo), "=f"(hi) : "l"(v));
}

// ---------------- amax reduction ----------------
__global__ void amax_kernel(const float* __restrict__ p, int n, unsigned* out) {
    float m = 0.f;
    for (int i = blockIdx.x * blockDim.x + threadIdx.x; i < n; i += gridDim.x * blockDim.x)
        m = fmaxf(m, fabsf(p[i]));
#pragma unroll
    for (int o = 16; o; o >>= 1) m = fmaxf(m, __shfl_xor_sync(0xFFFFFFFFu, m, o));
    if ((threadIdx.x & 31) == 0) atomicMax(out, __float_as_uint(m));
}

// ---------------- quantize helpers ----------------
__device__ __forceinline__ void quant16(const float* x, float s, unsigned& ph, unsigned& pl) {
    ph = 0; pl = 0;
#pragma unroll
    for (int j = 0; j < 4; j++) {
        float v = x[j] * s;
        float qh = rintf(v * (1.f / 256.f));
        qh = fminf(fmaxf(qh, -127.f), 127.f);
        float ql = rintf(v - 256.f * qh);
        ql = fminf(fmaxf(ql, -127.f), 127.f);
        ph |= ((unsigned)(unsigned char)(signed char)(int)qh) << (8 * j);
        pl |= ((unsigned)(unsigned char)(signed char)(int)ql) << (8 * j);
    }
}

__global__ void quantA_kernel(const float* __restrict__ X, int8_t* __restrict__ q,
                              int KT, const unsigned* __restrict__ ab, int ia) {
    int t = blockIdx.x * 256 + threadIdx.x;
    int lane = t & 31, atom = t >> 5;
    int kt = atom % KT, rt = atom / KT;
    int K = KT * 32;
    float s = 32512.f / __uint_as_float(ab[ia]);
    int r = rt * 16 + (lane >> 2);
    int c = kt * 32 + 4 * (lane & 3);
    const float* base = X + (size_t)r * K + c;
    float4 f0 = *reinterpret_cast<const float4*>(base);
    float4 f1 = *reinterpret_cast<const float4*>(base + (size_t)8 * K);
    float4 f2 = *reinterpret_cast<const float4*>(base + 16);
    float4 f3 = *reinterpret_cast<const float4*>(base + (size_t)8 * K + 16);
    uint4 hi, lo;
    quant16(&f0.x, s, hi.x, lo.x);
    quant16(&f1.x, s, hi.y, lo.y);
    quant16(&f2.x, s, hi.z, lo.z);
    quant16(&f3.x, s, hi.w, lo.w);
    size_t off = ((size_t)rt * KT + kt) * 512 + lane * 16;
    size_t limb = (size_t)MT_A * KT * 512;
    *reinterpret_cast<uint4*>(q + off) = hi;
    *reinterpret_cast<uint4*>(q + limb + off) = lo;
}

__global__ void quantB_kernel(const float* __restrict__ W, int8_t* __restrict__ q,
                              int NPT, int KT, int Nreal,
                              const unsigned* __restrict__ ab, int ib) {
    int t = blockIdx.x * 256 + threadIdx.x;
    int lane = t & 31, atom = t >> 5;
    int kt = atom % KT, np = atom / KT;
    float s = 32512.f / __uint_as_float(ab[ib]);
    int n0 = np * 16 + (lane >> 2);
    int n1 = n0 + 8;
    int kb = kt * 32 + 4 * (lane & 3);
    float g[4][4];
#pragma unroll
    for (int j = 0; j < 4; j++) {
        g[0][j] = (n0 < Nreal) ? W[(size_t)(kb + j) * Nreal + n0] : 0.f;
        g[1][j] = (n0 < Nreal) ? W[(size_t)(kb + 16 + j) * Nreal + n0] : 0.f;
        g[2][j] = (n1 < Nreal) ? W[(size_t)(kb + j) * Nreal + n1] : 0.f;
        g[3][j] = (n1 < Nreal) ? W[(size_t)(kb + 16 + j) * Nreal + n1] : 0.f;
    }
    uint4 hi, lo;
    quant16(g[0], s, hi.x, lo.x);
    quant16(g[1], s, hi.y, lo.y);
    quant16(g[2], s, hi.z, lo.z);
    quant16(g[3], s, hi.w, lo.w);
    size_t off = ((size_t)np * KT + kt) * 512 + lane * 16;
    size_t limb = (size_t)NPT * KT * 512;
    *reinterpret_cast<uint4*>(q + off) = hi;
    *reinterpret_cast<uint4*>(q + limb + off) = lo;
}

// ---------------- int8 2-limb GEMM, FULL 4 products (hh, hl, lh, ll) ----------------
// CTA 64x128, k-chunk 128 (4 atoms), 3-stage cp.async ring, 8 warps of 32x32.
// stage layout: A limb0 [0,8K), A limb1 [8K,16K), B limb0 [16K,32K), B limb1 [32K,48K)
__global__ __launch_bounds__(256, 1) void imma_gemm_kernel(
    const int8_t* __restrict__ qA, const int8_t* __restrict__ qB, float* __restrict__ C,
    int NPT, int KT, int N, int ldc, const unsigned* __restrict__ ab, int ia, int ib)
{
    extern __shared__ char smem[];
    const uint32_t sb = smem_u32(smem);
    const int tid = threadIdx.x, wid = tid >> 5, lane = tid & 31;
    const int wr = wid & 1, wc = wid >> 1;       // warp tile: rows wr*32, cols wc*32
    const int rt0 = blockIdx.y * 4;              // 4 row atoms per CTA
    const int np0 = blockIdx.x * 8;              // 8 n-pairs per CTA
    const int KC = KT >> 2;
    const size_t limbA = (size_t)MT_A * KT * 512;
    const size_t limbB = (size_t)NPT * KT * 512;

    int acH[2][4][4], acC[2][4][4], acL[2][4][4];
#pragma unroll
    for (int mi = 0; mi < 2; mi++)
#pragma unroll
        for (int ni = 0; ni < 4; ni++)
#pragma unroll
            for (int j = 0; j < 4; j++) { acH[mi][ni][j] = 0; acC[mi][ni][j] = 0; acL[mi][ni][j] = 0; }

    auto issue_chunk = [&](int ii) {
        const uint32_t st = (uint32_t)(ii % 3) * 49152u;
#pragma unroll
        for (int v = 0; v < 12; v++) {
            const int idx = v * 256 + tid;
            if (idx < 1024) {                 // A: 2 limbs x 4 ma x 4 ka x 32 seg
                const int limb = idx >> 9, r = idx & 511;
                const int ma = r >> 7, ka = (r >> 5) & 3, ln = r & 31;
                size_t ga = ((size_t)(rt0 + ma) * KT + (ii * 4 + ka)) * 512 +
                            (limb ? limbA : 0) + ln * 16;
                CP_ASYNC16(sb + st + (uint32_t)limb * 8192u + (uint32_t)(((ma * 4 + ka) << 9) + ln * 16),
                           qA + ga);
            } else {                          // B: 2 limbs x 8 np x 4 ka x 32 seg
                const int j = idx - 1024;
                const int limb = j >> 10, r = j & 1023;
                const int np = r >> 7, ka = (r >> 5) & 3, ln = r & 31;
                size_t gb = ((size_t)(np0 + np) * KT + (ii * 4 + ka)) * 512 +
                            (limb ? limbB : 0) + ln * 16;
                CP_ASYNC16(sb + st + 16384u + (uint32_t)limb * 16384u +
                           (uint32_t)(((np * 4 + ka) << 9) + ln * 16), qB + gb);
            }
        }
    };

    issue_chunk(0); CP_COMMIT();
    issue_chunk(1); CP_COMMIT();

    for (int i = 0; i < KC; i++) {
        if (i == KC - 1) { CP_WAIT0(); } else { CP_WAIT1(); }
        __syncthreads();
        if (i + 2 < KC) { issue_chunk(i + 2); CP_COMMIT(); }

        const uint32_t st = sb + (uint32_t)(i % 3) * 49152u;
#pragma unroll
        for (int ka = 0; ka < 4; ka++) {
            uint4 av[2][2], bv[2][2];
#pragma unroll
            for (int limb = 0; limb < 2; limb++) {
#pragma unroll
                for (int mi = 0; mi < 2; mi++)
                    av[limb][mi] = lds128(st + (uint32_t)limb * 8192u +
                                          ((((wr * 2 + mi) * 4 + ka)) << 9) + (lane << 4));
#pragma unroll
                for (int j = 0; j < 2; j++)
                    bv[limb][j] = lds128(st + 16384u + (uint32_t)limb * 16384u +
                                         ((((wc * 2 + j) * 4 + ka)) << 9) + (lane << 4));
            }
#pragma unroll
            for (int mi = 0; mi < 2; mi++)
#pragma unroll
                for (int j = 0; j < 2; j++)
#pragma unroll
                    for (int sub = 0; sub < 2; sub++) {
                        const int ni = j * 2 + sub;
                        const uint32_t bh0 = sub ? bv[0][j].z : bv[0][j].x;
                        const uint32_t bh1 = sub ? bv[0][j].w : bv[0][j].y;
                        const uint32_t bl0 = sub ? bv[1][j].z : bv[1][j].x;
                        const uint32_t bl1 = sub ? bv[1][j].w : bv[1][j].y;
                        IMMA16832(acH[mi][ni], av[0][mi], bh0, bh1);
                        IMMA16832(acC[mi][ni], av[0][mi], bl0, bl1);
                        IMMA16832(acC[mi][ni], av[1][mi], bh0, bh1);
                        IMMA16832(acL[mi][ni], av[1][mi], bl0, bl1);
                    }
        }
    }

    const float sa = __uint_as_float(ab[ia]) * (1.f / 32512.f);
    const float sbv = __uint_as_float(ab[ib]) * (1.f / 32512.f);
    const float sab = sa * sbv;
#pragma unroll
    for (int mi = 0; mi < 2; mi++) {
        const int row = blockIdx.y * 64 + wr * 32 + mi * 16 + (lane >> 2);
#pragma unroll
        for (int ni = 0; ni < 4; ni++) {
            const int col = blockIdx.x * 128 + wc * 32 + (ni >> 1) * 16 + (ni & 1) * 8 + 2 * (lane & 3);
            if (col < N) {
                float v0 = sab * (65536.f * (float)acH[mi][ni][0] + 256.f * (float)acC[mi][ni][0] + (float)acL[mi][ni][0]);
                float v1 = sab * (65536.f * (float)acH[mi][ni][1] + 256.f * (float)acC[mi][ni][1] + (float)acL[mi][ni][1]);
                float v2 = sab * (65536.f * (float)acH[mi][ni][2] + 256.f * (float)acC[mi][ni][2] + (float)acL[mi][ni][2]);
                float v3 = sab * (65536.f * (float)acH[mi][ni][3] + 256.f * (float)acC[mi][ni][3] + (float)acL[mi][ni][3]);
                *reinterpret_cast<float2*>(&C[(size_t)row * ldc + col]) = make_float2(v0, v1);
                *reinterpret_cast<float2*>(&C[(size_t)(row + 8) * ldc + col]) = make_float2(v2, v3);
            }
        }
    }
}

// ---------------- exact fp32 dt: raw = u @ W_in[:, -32:], softplus(+bias) -> g_dt ----------------
__global__ __launch_bounds__(256) void dt_exact_kernel(const float* __restrict__ u,
                                                       const float* __restrict__ W_in,
                                                       const float* __restrict__ dt_bias) {
    __shared__ float us[16 * 256];
    __shared__ float ws[256 * 32];
    const int m0 = blockIdx.x * 16;
    const int t = threadIdx.x;
    const int mloc = t >> 4, h0 = t & 15, h1 = 16 + (t & 15);
    float acc0 = 0.f, acc1 = 0.f;
    for (int kc = 0; kc < 4; kc++) {
        __syncthreads();
        for (int i = t; i < 4096; i += 256) {
            int mm = i >> 8, kk = i & 255;
            us[i] = u[(size_t)(m0 + mm) * DMODEL + kc * 256 + kk];
        }
        for (int i = t; i < 8192; i += 256) {
            int kk = i >> 5, hh = i & 31;
            ws[i] = W_in[(size_t)(kc * 256 + kk) * DPROJ + (DPROJ - NH) + hh];
        }
        __syncthreads();
#pragma unroll 8
        for (int kk = 0; kk < 256; kk++) {
            float uv = us[mloc * 256 + kk];
            acc0 = fmaf(uv, ws[kk * 32 + h0], acc0);
            acc1 = fmaf(uv, ws[kk * 32 + h1], acc1);
        }
    }
    float x0 = acc0 + dt_bias[h0];
    float x1 = acc1 + dt_bias[h1];
    g_dt[(m0 + mloc) * NH + h0] = (x0 > 20.f) ? x0 : log1pf(expf(x0));
    g_dt[(m0 + mloc) * NH + h1] = (x1 > 20.f) ? x1 : log1pf(expf(x1));
}

// ---------------- per (b,c,h): cumsum of A*dt over chunk ----------------
__global__ void acum_kernel(const float* __restrict__ A_log) {
    int idx = blockIdx.x * blockDim.x + threadIdx.x;
    if (idx >= BQ * NC * NH) return;
    int h = idx & 31;
    int c = (idx >> 5) & 63;
    int b = idx >> 11;
    float A = -expf(A_log[h]);
    int m0 = b * LSEQ + c * CHK;
    float cum = 0.f;
    for (int l = 0; l < CHK; l++) {
        cum += A * g_dt[(m0 + l) * NH + h];
        g_acum[idx * CHK + l] = cum;
    }
    g_suma[idx] = expf(cum);
}

// ---------------- depthwise causal conv(4) + bias + SiLU (smem-tiled) ----------------
__global__ __launch_bounds__(256) void conv_kernel(const float* __restrict__ cw,
                                                   const float* __restrict__ cb) {
    __shared__ float s[19][256];
    int tid = threadIdx.x;
    int ch = blockIdx.x * 256 + tid;
    int m0 = blockIdx.y * 16;
    int l0 = m0 & (LSEQ - 1);
#pragma unroll
    for (int r = 0; r < 19; r++) {
        int l = l0 - 3 + r;
        s[r][tid] = (l >= 0) ? g_zx[(size_t)(m0 - 3 + r) * DPROJ + DINNER + ch] : 0.f;
    }
    __syncthreads();
    float w0 = cw[ch * 4], w1 = cw[ch * 4 + 1], w2 = cw[ch * 4 + 2], w3 = cw[ch * 4 + 3];
    float bias = cb[ch];
#pragma unroll
    for (int r = 0; r < 16; r++) {
        float acc = bias;
        acc = fmaf(s[r][tid], w0, acc);
        acc = fmaf(s[r + 1][tid], w1, acc);
        acc = fmaf(s[r + 2][tid], w2, acc);
        acc = fmaf(s[r + 3][tid], w3, acc);
        g_xbc[(size_t)(m0 + r) * CONVCH + ch] = acc / (1.f + expf(-acc));
    }
}

// ---------------- SSD intra-chunk: Y_diag + local states (f32x2 + triangular) ----------------
#define TS_STR 66
#define CS_STR 132
#define XS_STR 68
__global__ __launch_bounds__(256, 1) void ssd_diag_kernel() {
    int blk = blockIdx.x;
    int h = blk & 31;
    int c = (blk >> 5) & 63;
    int b = blk >> 11;
    int m0 = b * LSEQ + c * CHK;

    extern __shared__ float sm[];
    float* Bst = sm;
    float* Cs  = Bst + 128 * TS_STR;
    float* xs  = Cs + 64 * CS_STR;
    float* Gs  = xs + 64 * XS_STR;
    float* ac  = Gs + 64 * XS_STR;
    float* wd  = ac + 64;
    int tid = threadIdx.x;

    for (int i = tid; i < 64 * 128; i += 256) {
        int l = i >> 7, n = i & 127;
        Bst[n * TS_STR + l] = g_xbc[(size_t)(m0 + l) * CONVCH + DINNER + n];
    }
    for (int i = tid; i < 64 * 32; i += 256) {
        int l = i >> 5, q = i & 31;
        float4 v = *reinterpret_cast<const float4*>(
            g_xbc + (size_t)(m0 + l) * CONVCH + DINNER + DSTATE + 4 * q);
        *reinterpret_cast<float4*>(Cs + l * CS_STR + 4 * q) = v;
    }
    for (int i = tid; i < 64 * 16; i += 256) {
        int l = i >> 4, q = i & 15;
        float dtv = g_dt[(m0 + l) * NH + h];
        float4 v = *reinterpret_cast<const float4*>(
            g_xbc + (size_t)(m0 + l) * CONVCH + h * HD + 4 * q);
        v.x *= dtv; v.y *= dtv; v.z *= dtv; v.w *= dtv;
        *reinterpret_cast<float4*>(xs + l * XS_STR + 4 * q) = v;
    }
    if (tid < 64) ac[tid] = g_acum[blk * CHK + tid];
    __syncthreads();
    if (tid < 64) wd[tid] = expf(ac[63] - ac[tid]);

    const int tr = tid >> 4, tc = tid & 15;
    const int r0 = tr * 4, c0 = tc * 4;

    if (tc <= tr) {
        uint64_t acc2[4][2] = {{0ull,0ull},{0ull,0ull},{0ull,0ull},{0ull,0ull}};
        for (int n4 = 0; n4 < 128; n4 += 4) {
            float4 cr[4];
#pragma unroll
            for (int i = 0; i < 4; i++)
                cr[i] = *reinterpret_cast<const float4*>(Cs + (r0 + i) * CS_STR + n4);
#pragma unroll
            for (int nn = 0; nn < 4; nn++) {
                uint64_t b0 = *reinterpret_cast<const uint64_t*>(Bst + (n4 + nn) * TS_STR + c0);
                uint64_t b1 = *reinterpret_cast<const uint64_t*>(Bst + (n4 + nn) * TS_STR + c0 + 2);
#pragma unroll
                for (int i = 0; i < 4; i++) {
                    uint64_t a2 = dup2((&cr[i].x)[nn]);
                    FMA2(acc2[i][0], a2, b0);
                    FMA2(acc2[i][1], a2, b1);
                }
            }
        }
#pragma unroll
        for (int i = 0; i < 4; i++) {
            int l = r0 + i;
            float al = ac[l];
            float v0, v1, v2, v3;
            up2(acc2[i][0], v0, v1);
            up2(acc2[i][1], v2, v3);
            float4 o;
            o.x = (c0     <= l) ? v0 * expf(al - ac[c0])     : 0.f;
            o.y = (c0 + 1 <= l) ? v1 * expf(al - ac[c0 + 1]) : 0.f;
            o.z = (c0 + 2 <= l) ? v2 * expf(al - ac[c0 + 2]) : 0.f;
            o.w = (c0 + 3 <= l) ? v3 * expf(al - ac[c0 + 3]) : 0.f;
            *reinterpret_cast<float4*>(Gs + l * XS_STR + c0) = o;
        }
    }
    __syncthreads();

    {
        uint64_t acc2[4][2] = {{0ull,0ull},{0ull,0ull},{0ull,0ull},{0ull,0ull}};
        for (int s4 = 0; s4 < r0 + 4; s4 += 4) {
            float4 gr[4];
#pragma unroll
            for (int i = 0; i < 4; i++)
                gr[i] = *reinterpret_cast<const float4*>(Gs + (r0 + i) * XS_STR + s4);
#pragma unroll
            for (int ss = 0; ss < 4; ss++) {
                uint64_t x0 = *reinterpret_cast<const uint64_t*>(xs + (s4 + ss) * XS_STR + c0);
                uint64_t x1 = *reinterpret_cast<const uint64_t*>(xs + (s4 + ss) * XS_STR + c0 + 2);
#pragma unroll
                for (int i = 0; i < 4; i++) {
                    uint64_t a2 = dup2((&gr[i].x)[ss]);
                    FMA2(acc2[i][0], a2, x0);
                    FMA2(acc2[i][1], a2, x1);
                }
            }
        }
#pragma unroll
        for (int i = 0; i < 4; i++) {
            float v0, v1, v2, v3;
            up2(acc2[i][0], v0, v1);
            up2(acc2[i][1], v2, v3);
            *reinterpret_cast<float4*>(g_y + (size_t)(m0 + r0 + i) * DINNER + h * HD + c0) =
                make_float4(v0, v1, v2, v3);
        }
    }

    {
        const int p0 = (tid & 15) * 4, n0 = (tid >> 4) * 8;
        uint64_t acc2[2][8];
#pragma unroll
        for (int pp = 0; pp < 2; pp++)
#pragma unroll
            for (int j = 0; j < 8; j++) acc2[pp][j] = 0ull;
        for (int l = 0; l < 64; l++) {
            uint64_t w2 = dup2(wd[l]);
            uint64_t xa = *reinterpret_cast<const uint64_t*>(xs + l * XS_STR + p0);
            uint64_t xb = *reinterpret_cast<const uint64_t*>(xs + l * XS_STR + p0 + 2);
            uint64_t wxa, wxb;
            MUL2(wxa, xa, w2);
            MUL2(wxb, xb, w2);
#pragma unroll
            for (int j = 0; j < 8; j++) {
                uint64_t b2 = dup2(Bst[(n0 + j) * TS_STR + l]);
                FMA2(acc2[0][j], wxa, b2);
                FMA2(acc2[1][j], wxb, b2);
            }
        }
        float rowv[4][8];
#pragma unroll
        for (int pp = 0; pp < 2; pp++)
#pragma unroll
            for (int j = 0; j < 8; j++)
                up2(acc2[pp][j], rowv[2 * pp][j], rowv[2 * pp + 1][j]);
#pragma unroll
        for (int i = 0; i < 4; i++) {
            float* dst = g_states + ((size_t)blk * HD + p0 + i) * DSTATE + n0;
            *reinterpret_cast<float4*>(dst)     = make_float4(rowv[i][0], rowv[i][1], rowv[i][2], rowv[i][3]);
            *reinterpret_cast<float4*>(dst + 4) = make_float4(rowv[i][4], rowv[i][5], rowv[i][6], rowv[i][7]);
        }
    }
}

// ---------------- inter-chunk scan ----------------
__global__ void scan_kernel() {
    int idx = blockIdx.x * blockDim.x + threadIdx.x;
    int n = idx & 127;
    int p = (idx >> 7) & 63;
    int h = (idx >> 13) & 31;
    int b = idx >> 18;
    float prev = 0.f;
    for (int c = 0; c < NC; c++) {
        int bch = (b * NC + c) * NH + h;
        size_t off = ((size_t)bch * HD + p) * DSTATE + n;
        float loc = g_states[off];
        g_states[off] = prev;
        prev = fmaf(prev, g_suma[bch], loc);
    }
}

// ---------------- Y_off + skip (f32x2) ----------------
__global__ __launch_bounds__(256, 1) void yoff_kernel(const float* __restrict__ Dv) {
    int blk = blockIdx.x;
    int h = blk & 31;
    int c = (blk >> 5) & 63;
    int b = blk >> 11;
    int m0 = b * LSEQ + c * CHK;

    extern __shared__ float sm[];
    float* Pst = sm;
    float* Cs  = Pst + 128 * TS_STR;
    float* ac  = Cs + 64 * CS_STR;
    int tid = threadIdx.x;

    for (int i = tid; i < 64 * 128; i += 256) {
        int p = i >> 7, n = i & 127;
        Pst[n * TS_STR + p] = g_states[((size_t)blk * HD + p) * DSTATE + n];
    }
    for (int i = tid; i < 64 * 32; i += 256) {
        int l = i >> 5, q = i & 31;
        float4 v = *reinterpret_cast<const float4*>(
            g_xbc + (size_t)(m0 + l) * CONVCH + DINNER + DSTATE + 4 * q);
        *reinterpret_cast<float4*>(Cs + l * CS_STR + 4 * q) = v;
    }
    if (tid < 64) ac[tid] = g_acum[blk * CHK + tid];
    float Dh = Dv[h];
    __syncthreads();

    const int tr = tid >> 4, tc = tid & 15;
    const int r0 = tr * 4, c0 = tc * 4;
    uint64_t acc2[4][2] = {{0ull,0ull},{0ull,0ull},{0ull,0ull},{0ull,0ull}};
    for (int n4 = 0; n4 < 128; n4 += 4) {
        float4 cr[4];
#pragma unroll
        for (int i = 0; i < 4; i++)
            cr[i] = *reinterpret_cast<const float4*>(Cs + (r0 + i) * CS_STR + n4);
#pragma unroll
        for (int nn = 0; nn < 4; nn++) {
            uint64_t p0v = *reinterpret_cast<const uint64_t*>(Pst + (n4 + nn) * TS_STR + c0);
            uint64_t p1v = *reinterpret_cast<const uint64_t*>(Pst + (n4 + nn) * TS_STR + c0 + 2);
#pragma unroll
            for (int i = 0; i < 4; i++) {
                uint64_t a2 = dup2((&cr[i].x)[nn]);
                FMA2(acc2[i][0], a2, p0v);
                FMA2(acc2[i][1], a2, p1v);
            }
        }
    }
#pragma unroll
    for (int i = 0; i < 4; i++) {
        int l = r0 + i;
        int row = m0 + l;
        float el = expf(ac[l]);
        float v0, v1, v2, v3;
        up2(acc2[i][0], v0, v1);
        up2(acc2[i][1], v2, v3);
        float4 xv = *reinterpret_cast<const float4*>(
            g_xbc + (size_t)row * CONVCH + h * HD + c0);
        float4* yp = reinterpret_cast<float4*>(g_y + (size_t)row * DINNER + h * HD + c0);
        float4 yv = *yp;
        yv.x += v0 * el + xv.x * Dh;
        yv.y += v1 * el + xv.y * Dh;
        yv.z += v2 * el + xv.z * Dh;
        yv.w += v3 * el + xv.w * Dh;
        *yp = yv;
    }
}

// ---------------- gate (silu(z)) + RMSNorm -> fp32 y ----------------
__global__ void gate_kernel(const float* __restrict__ norm_w) {
    int m = blockIdx.x;
    int tid = threadIdx.x;
    __shared__ float red[256];
    float tv[8];
    float ss = 0.f;
#pragma unroll
    for (int j = 0; j < 8; j++) {
        int i = tid + 256 * j;
        float zv = g_zx[(size_t)m * DPROJ + i];
        float yv = g_y[(size_t)m * DINNER + i];
        float g = yv * (zv / (1.f + expf(-zv)));
        tv[j] = g;
        ss += g * g;
    }
    red[tid] = ss;
    __syncthreads();
    for (int s = 128; s > 0; s >>= 1) {
        if (tid < s) red[tid] += red[tid + s];
        __syncthreads();
    }
    float scale = rsqrtf(red[0] / (float)DINNER + 1e-5f);
#pragma unroll
    for (int j = 0; j < 8; j++) {
        int i = tid + 256 * j;
        g_y[(size_t)m * DINNER + i] = tv[j] * scale * norm_w[i];
    }
}

// ---------------- launch ----------------
extern "C" void kernel_launch(void* const* d_in, const int* in_sizes, int n_in,
                              void* d_out, int out_size) {
    const float* u      = (const float*)d_in[0];
    const float* W_in   = (const float*)d_in[1];
    const float* conv_w = (const float*)d_in[2];
    const float* conv_b = (const float*)d_in[3];
    const float* dt_b   = (const float*)d_in[4];
    const float* A_log  = (const float*)d_in[5];
    const float* Dv     = (const float*)d_in[6];
    const float* norm_w = (const float*)d_in[7];
    const float* W_out  = (const float*)d_in[8];
    float* out = (float*)d_out;

    float *zx = nullptr, *ybuf = nullptr;
    cudaGetSymbolAddress((void**)&zx, g_zx);
    cudaGetSymbolAddress((void**)&ybuf, g_y);
    unsigned* am = nullptr;
    cudaGetSymbolAddress((void**)&am, g_amax);
    int8_t *qa1, *qb1, *qa2, *qb2;
    cudaGetSymbolAddress((void**)&qa1, g_qa1);
    cudaGetSymbolAddress((void**)&qb1, g_qb1);
    cudaGetSymbolAddress((void**)&qa2, g_qa2);
    cudaGetSymbolAddress((void**)&qb2, g_qb2);

    const size_t gemm_smem = 3 * 49152;   // 147456
    const size_t diag_smem = (size_t)(128 * TS_STR + 64 * CS_STR + 2 * 64 * XS_STR + 128) * sizeof(float);
    const size_t yoff_smem = (size_t)(128 * TS_STR + 64 * CS_STR + 64) * sizeof(float);
    cudaFuncSetAttribute(imma_gemm_kernel, cudaFuncAttributeMaxDynamicSharedMemorySize, (int)gemm_smem);
    cudaFuncSetAttribute(ssd_diag_kernel, cudaFuncAttributeMaxDynamicSharedMemorySize, (int)diag_smem);
    cudaFuncSetAttribute(yoff_kernel, cudaFuncAttributeMaxDynamicSharedMemorySize, (int)yoff_smem);

    // 0-2: amax reductions (monotone atomicMax -> deterministic across graph replays)
    amax_kernel<<<512, 256>>>(u, MROWS * DMODEL, am + 0);
    amax_kernel<<<512, 256>>>(W_in, DMODEL * DPROJ, am + 1);
    amax_kernel<<<512, 256>>>(W_out, DINNER * DMODEL, am + 2);

    // 3-4: quantize GEMM1 operands
    quantA_kernel<<<MT_A * KT1 * 32 / 256, 256>>>(u, qa1, KT1, am, 0);
    quantB_kernel<<<NPT1 * KT1 * 32 / 256, 256>>>(W_in, qb1, NPT1, KT1, DPROJ, am, 1);

    // 5: GEMM1 (int8, 4 products): zx[8192,4384] = u @ W_in  <- ncu capture target
    imma_gemm_kernel<<<dim3(NPT1 / 8, MROWS / 64), 256, gemm_smem>>>(
        qa1, qb1, zx, NPT1, KT1, DPROJ, DPROJ, am, 0, 1);

    // 6: exact fp32 dt
    dt_exact_kernel<<<MROWS / 16, 256>>>(u, W_in, dt_b);

    acum_kernel<<<BQ * NC * NH / 256, 256>>>(A_log);
    conv_kernel<<<dim3(CONVCH / 256, MROWS / 16), 256>>>(conv_w, conv_b);
    ssd_diag_kernel<<<BQ * NC * NH, 256, diag_smem>>>();
    scan_kernel<<<(BQ * NH * HD * DSTATE) / 256, 256>>>();
    yoff_kernel<<<BQ * NC * NH, 256, yoff_smem>>>(Dv);
    gate_kernel<<<MROWS, 256>>>(norm_w);

    // GEMM2 operands
    amax_kernel<<<512, 256>>>(ybuf, MROWS * DINNER, am + 3);
    quantA_kernel<<<MT_A * KT2 * 32 / 256, 256>>>(ybuf, qa2, KT2, am, 3);
    quantB_kernel<<<NPT2 * KT2 * 32 / 256, 256>>>(W_out, qb2, NPT2, KT2, DMODEL, am, 2);

    // GEMM2 (int8, 4 products): out[8192,1024] = y @ W_out
    imma_gemm_kernel<<<dim3(NPT2 / 8, MROWS / 64), 256, gemm_smem>>>(
        qa2, qb2, out, NPT2, KT2, DMODEL, DMODEL, am, 3, 2);
}

// round 9
// speedup vs baseline: 1.9594x; 1.9594x over previous
#include <cuda_runtime.h>
#include <cuda_bf16.h>
#include <math.h>
#include <cstdint>

// ---------------- problem constants ----------------
#define BQ 2
#define LSEQ 4096
#define DMODEL 1024
#define DINNER 2048
#define NH 32
#define HD 64
#define DSTATE 128
#define CHK 64
#define NC 64
#define DPROJ 4384
#define CONVCH 2304
#define MROWS (BQ*LSEQ)
#define NPAD1 4480      // DPROJ padded to 128

// ---------------- scratch (device globals; no allocation) ----------------
__device__ float g_zx[(size_t)MROWS * DPROJ];
__device__ float g_xbc[(size_t)MROWS * CONVCH];
__device__ float g_dt[MROWS * NH];
__device__ float g_acum[BQ * NC * NH * CHK];
__device__ float g_suma[BQ * NC * NH];
__device__ float g_states[(size_t)BQ * NC * NH * HD * DSTATE];
__device__ float g_y[(size_t)MROWS * DINNER];

__device__ __nv_bfloat16 g_a1h[(size_t)MROWS * DMODEL];
__device__ __nv_bfloat16 g_a1l[(size_t)MROWS * DMODEL];
__device__ __nv_bfloat16 g_b1h[(size_t)NPAD1 * DMODEL];
__device__ __nv_bfloat16 g_b1l[(size_t)NPAD1 * DMODEL];
__device__ __nv_bfloat16 g_a2h[(size_t)MROWS * DINNER];
__device__ __nv_bfloat16 g_a2l[(size_t)MROWS * DINNER];
__device__ __nv_bfloat16 g_b2h[(size_t)DMODEL * DINNER];
__device__ __nv_bfloat16 g_b2l[(size_t)DMODEL * DINNER];

// ---------------- PTX helpers ----------------
__device__ __forceinline__ uint32_t smem_u32(const void* p) {
    uint32_t a;
    asm("{ .reg .u64 t; cvta.to.shared.u64 t, %1; cvt.u32.u64 %0, t; }" : "=r"(a) : "l"(p));
    return a;
}
#define SMEM_SWIZZLE_128B(byte_offset) ((byte_offset) ^ (((byte_offset) >> 3) & 0x70))
#define CP_ASYNC16(dst, src) \
    asm volatile("cp.async.cg.shared.global [%0], [%1], 16;" :: "r"(dst), "l"(src) : "memory")
#define CP_COMMIT() asm volatile("cp.async.commit_group;" ::: "memory")
#define CP_WAIT0()  asm volatile("cp.async.wait_group 0;" ::: "memory")

#define LDSM_X4(r0,r1,r2,r3,addr) \
    asm volatile("ldmatrix.sync.aligned.m8n8.x4.shared.b16 {%0,%1,%2,%3}, [%4];" \
        : "=r"(r0), "=r"(r1), "=r"(r2), "=r"(r3) : "r"(addr))

#define MMA16816(d, a, b0, b1) \
    asm volatile("mma.sync.aligned.m16n8k16.row.col.f32.bf16.bf16.f32 " \
        "{%0,%1,%2,%3}, {%4,%5,%6,%7}, {%8,%9}, {%0,%1,%2,%3};" \
        : "+f"((d)[0]), "+f"((d)[1]), "+f"((d)[2]), "+f"((d)[3]) \
        : "r"((a)[0]), "r"((a)[1]), "r"((a)[2]), "r"((a)[3]), "r"(b0), "r"(b1))

// packed f32x2 (2x fp32 FMA rate) for SSD kernels
#define FMA2(d, a, b) asm("fma.rn.f32x2 %0, %1, %2, %0;" : "+l"(d) : "l"(a), "l"(b))
#define MUL2(d, a, b) asm("mul.rn.f32x2 %0, %1, %2;" : "=l"(d) : "l"(a), "l"(b))
__device__ __forceinline__ uint64_t dup2(float x) {
    uint64_t r; asm("mov.b64 %0, {%1, %1};" : "=l"(r) : "f"(x)); return r;
}
__device__ __forceinline__ void up2(uint64_t v, float& lo, float& hi) {
    asm("mov.b64 {%0, %1}, %2;" : "=f"(lo), "=f"(hi) : "l"(v));
}

__device__ __forceinline__ void ldsmA(uint32_t base, int row, int ks, int lane, uint32_t* r) {
    int rr = row + (lane & 15);
    int off = rr * 128 + ks * 32 + ((lane >> 4) << 4);
    LDSM_X4(r[0], r[1], r[2], r[3], base + SMEM_SWIZZLE_128B((uint32_t)off));
}
// NON-trans: Bt stored [n][k] k-contiguous gives col-major B frags.
__device__ __forceinline__ void ldsmB(uint32_t base, int nrow, int ks, int lane, uint32_t* r) {
    int n = nrow + ((lane >> 4) << 3) + (lane & 7);
    int off = n * 128 + ks * 32 + (((lane >> 3) & 1) << 4);
    LDSM_X4(r[0], r[1], r[2], r[3], base + SMEM_SWIZZLE_128B((uint32_t)off));
}

// ---------------- HMMA split-bf16 GEMM: C[M,N] = A[M,K] @ Bt[N,K]^T ----------------
// CTA 128x64, K-chunk 64 bf16, 2-stage cp.async ring, 8 warps of 32x32, 2 CTAs/SM.
// stage layout: Ah [0,16K), Al [16K,32K), Bh [32K,40K), Bl [40K,48K)
__global__ __launch_bounds__(256, 2) void hmma_gemm_kernel(
    const __nv_bfloat16* __restrict__ Ah, const __nv_bfloat16* __restrict__ Al,
    const __nv_bfloat16* __restrict__ Bh, const __nv_bfloat16* __restrict__ Bl,
    float* __restrict__ C, int N, int K, int ldc)
{
    extern __shared__ char smem[];
    const uint32_t sb = smem_u32(smem);
    const int tid = threadIdx.x, wid = tid >> 5, lane = tid & 31;
    const int wr = wid & 3, wc = wid >> 2;          // warp tile: rows wr*32, cols wc*32
    const int rowbase = blockIdx.y * 128, colbase = blockIdx.x * 64;
    const int KC = K >> 6;

    float acc[2][4][4];
#pragma unroll
    for (int mi = 0; mi < 2; mi++)
#pragma unroll
        for (int ni = 0; ni < 4; ni++)
#pragma unroll
            for (int j = 0; j < 4; j++) acc[mi][ni][j] = 0.f;

    auto issue_chunk = [&](int i) {
        const uint32_t st = (uint32_t)(i & 1) * 49152u;
        const int k0 = i << 6;
#pragma unroll
        for (int v = 0; v < 12; v++) {
            const int idx = v * 256 + tid;                 // 0..3071
            const __nv_bfloat16* src;
            uint32_t dst;
            if (idx < 2048) {                              // A: 2 bufs x 128 rows x 8 c8
                const int buf = idx >> 10;                 // 0:Ah 1:Al
                const int r = (idx & 1023) >> 3, c8 = idx & 7;
                src = (buf ? Al : Ah) + (size_t)(rowbase + r) * K + k0 + c8 * 8;
                dst = sb + st + (uint32_t)buf * 16384u +
                      SMEM_SWIZZLE_128B((uint32_t)(r * 128 + c8 * 16));
            } else {                                       // B: 2 bufs x 64 rows x 8 c8
                const int j = idx - 2048;
                const int buf = j >> 9;                    // 0:Bh 1:Bl
                const int r = (j & 511) >> 3, c8 = j & 7;
                src = (buf ? Bl : Bh) + (size_t)(colbase + r) * K + k0 + c8 * 8;
                dst = sb + st + 32768u + (uint32_t)buf * 8192u +
                      SMEM_SWIZZLE_128B((uint32_t)(r * 128 + c8 * 16));
            }
            CP_ASYNC16(dst, src);
        }
    };

    issue_chunk(0);
    CP_COMMIT();

    for (int i = 0; i < KC; i++) {
        CP_WAIT0();
        __syncthreads();
        if (i + 1 < KC) { issue_chunk(i + 1); CP_COMMIT(); }

        const uint32_t st = sb + (uint32_t)(i & 1) * 49152u;
        const uint32_t aH = st, aL = st + 16384u, bH = st + 32768u, bL = st + 40960u;
#pragma unroll
        for (int ks = 0; ks < 4; ks++) {
            uint32_t ah[2][4], al[2][4], bh[2][4], bl[2][4];
#pragma unroll
            for (int mi = 0; mi < 2; mi++) {
                ldsmA(aH, wr * 32 + mi * 16, ks, lane, ah[mi]);
                ldsmA(aL, wr * 32 + mi * 16, ks, lane, al[mi]);
            }
#pragma unroll
            for (int np = 0; np < 2; np++) {
                ldsmB(bH, wc * 32 + np * 16, ks, lane, bh[np]);
                ldsmB(bL, wc * 32 + np * 16, ks, lane, bl[np]);
            }
#pragma unroll
            for (int mi = 0; mi < 2; mi++)
#pragma unroll
                for (int ni = 0; ni < 4; ni++) {
                    const int np = ni >> 1, o = (ni & 1) << 1;
                    MMA16816(acc[mi][ni], ah[mi], bh[np][o], bh[np][o + 1]);
                    MMA16816(acc[mi][ni], ah[mi], bl[np][o], bl[np][o + 1]);
                    MMA16816(acc[mi][ni], al[mi], bh[np][o], bh[np][o + 1]);
                }
        }
        __syncthreads();
    }

    // epilogue: m16n8 D layout -> C
#pragma unroll
    for (int mi = 0; mi < 2; mi++) {
        const int row = rowbase + wr * 32 + mi * 16 + (lane >> 2);
#pragma unroll
        for (int ni = 0; ni < 4; ni++) {
            const int col = colbase + wc * 32 + ni * 8 + (lane & 3) * 2;
            if (col < N) {
                *reinterpret_cast<float2*>(&C[(size_t)row * ldc + col]) =
                    make_float2(acc[mi][ni][0], acc[mi][ni][1]);
                *reinterpret_cast<float2*>(&C[(size_t)(row + 8) * ldc + col]) =
                    make_float2(acc[mi][ni][2], acc[mi][ni][3]);
            }
        }
    }
}

// ---------------- fp32 -> (hi, lo) bf16 split ----------------
__global__ void cvt_split_kernel(const float* __restrict__ X, __nv_bfloat16* __restrict__ hi,
                                 __nv_bfloat16* __restrict__ lo, int n4) {
    int i = blockIdx.x * blockDim.x + threadIdx.x;
    if (i >= n4) return;
    float4 x = reinterpret_cast<const float4*>(X)[i];
    float xs[4] = {x.x, x.y, x.z, x.w};
    __nv_bfloat16 h[4], l[4];
#pragma unroll
    for (int j = 0; j < 4; j++) {
        h[j] = __float2bfloat16(xs[j]);
        l[j] = __float2bfloat16(xs[j] - __bfloat162float(h[j]));
    }
    reinterpret_cast<__nv_bfloat162*>(hi)[2 * i]     = __nv_bfloat162(h[0], h[1]);
    reinterpret_cast<__nv_bfloat162*>(hi)[2 * i + 1] = __nv_bfloat162(h[2], h[3]);
    reinterpret_cast<__nv_bfloat162*>(lo)[2 * i]     = __nv_bfloat162(l[0], l[1]);
    reinterpret_cast<__nv_bfloat162*>(lo)[2 * i + 1] = __nv_bfloat162(l[2], l[3]);
}

// ---------------- W[K,N] -> Bt[Npad,K] (hi,lo), zero-padded ----------------
__global__ void transpose_split_kernel(const float* __restrict__ W,
                                       __nv_bfloat16* __restrict__ th,
                                       __nv_bfloat16* __restrict__ tl, int K, int N) {
    __shared__ float t[32][33];
    int n = blockIdx.x * 32 + threadIdx.x;
    int k = blockIdx.y * 32 + threadIdx.y;
    t[threadIdx.y][threadIdx.x] = (n < N) ? W[(size_t)k * N + n] : 0.f;
    __syncthreads();
    int nn = blockIdx.x * 32 + threadIdx.y;
    int kk = blockIdx.y * 32 + threadIdx.x;
    float v = t[threadIdx.x][threadIdx.y];
    __nv_bfloat16 h = __float2bfloat16(v);
    th[(size_t)nn * K + kk] = h;
    tl[(size_t)nn * K + kk] = __float2bfloat16(v - __bfloat162float(h));
}

// ---------------- dt = softplus(raw + bias) ----------------
__global__ void dt_kernel(const float* __restrict__ dt_bias) {
    int idx = blockIdx.x * blockDim.x + threadIdx.x;
    int h = idx & 31;
    int m = idx >> 5;
    float x = g_zx[(size_t)m * DPROJ + (DPROJ - NH) + h] + dt_bias[h];
    g_dt[idx] = (x > 20.f) ? x : log1pf(expf(x));
}

// ---------------- per (b,c,h): cumsum of A*dt over chunk ----------------
__global__ void acum_kernel(const float* __restrict__ A_log) {
    int idx = blockIdx.x * blockDim.x + threadIdx.x;
    if (idx >= BQ * NC * NH) return;
    int h = idx & 31;
    int c = (idx >> 5) & 63;
    int b = idx >> 11;
    float A = -expf(A_log[h]);
    int m0 = b * LSEQ + c * CHK;
    float cum = 0.f;
    for (int l = 0; l < CHK; l++) {
        cum += A * g_dt[(m0 + l) * NH + h];
        g_acum[idx * CHK + l] = cum;
    }
    g_suma[idx] = expf(cum);
}

// ---------------- depthwise causal conv(4) + bias + SiLU (smem-tiled) ----------------
__global__ __launch_bounds__(256) void conv_kernel(const float* __restrict__ cw,
                                                   const float* __restrict__ cb) {
    __shared__ float s[19][256];
    int tid = threadIdx.x;
    int ch = blockIdx.x * 256 + tid;
    int m0 = blockIdx.y * 16;
    int l0 = m0 & (LSEQ - 1);
#pragma unroll
    for (int r = 0; r < 19; r++) {
        int l = l0 - 3 + r;
        s[r][tid] = (l >= 0) ? g_zx[(size_t)(m0 - 3 + r) * DPROJ + DINNER + ch] : 0.f;
    }
    __syncthreads();
    float w0 = cw[ch * 4], w1 = cw[ch * 4 + 1], w2 = cw[ch * 4 + 2], w3 = cw[ch * 4 + 3];
    float bias = cb[ch];
#pragma unroll
    for (int r = 0; r < 16; r++) {
        float acc = bias;
        acc = fmaf(s[r][tid], w0, acc);
        acc = fmaf(s[r + 1][tid], w1, acc);
        acc = fmaf(s[r + 2][tid], w2, acc);
        acc = fmaf(s[r + 3][tid], w3, acc);
        g_xbc[(size_t)(m0 + r) * CONVCH + ch] = acc / (1.f + expf(-acc));
    }
}

// ---------------- SSD intra-chunk: Y_diag + local states (f32x2 + triangular) ----------------
#define TS_STR 66
#define CS_STR 132
#define XS_STR 68
__global__ __launch_bounds__(256, 1) void ssd_diag_kernel() {
    int blk = blockIdx.x;
    int h = blk & 31;
    int c = (blk >> 5) & 63;
    int b = blk >> 11;
    int m0 = b * LSEQ + c * CHK;

    extern __shared__ float sm[];
    float* Bst = sm;
    float* Cs  = Bst + 128 * TS_STR;
    float* xs  = Cs + 64 * CS_STR;
    float* Gs  = xs + 64 * XS_STR;
    float* ac  = Gs + 64 * XS_STR;
    float* wd  = ac + 64;
    int tid = threadIdx.x;

    for (int i = tid; i < 64 * 128; i += 256) {
        int l = i >> 7, n = i & 127;
        Bst[n * TS_STR + l] = g_xbc[(size_t)(m0 + l) * CONVCH + DINNER + n];
    }
    for (int i = tid; i < 64 * 32; i += 256) {
        int l = i >> 5, q = i & 31;
        float4 v = *reinterpret_cast<const float4*>(
            g_xbc + (size_t)(m0 + l) * CONVCH + DINNER + DSTATE + 4 * q);
        *reinterpret_cast<float4*>(Cs + l * CS_STR + 4 * q) = v;
    }
    for (int i = tid; i < 64 * 16; i += 256) {
        int l = i >> 4, q = i & 15;
        float dtv = g_dt[(m0 + l) * NH + h];
        float4 v = *reinterpret_cast<const float4*>(
            g_xbc + (size_t)(m0 + l) * CONVCH + h * HD + 4 * q);
        v.x *= dtv; v.y *= dtv; v.z *= dtv; v.w *= dtv;
        *reinterpret_cast<float4*>(xs + l * XS_STR + 4 * q) = v;
    }
    if (tid < 64) ac[tid] = g_acum[blk * CHK + tid];
    __syncthreads();
    if (tid < 64) wd[tid] = expf(ac[63] - ac[tid]);

    const int tr = tid >> 4, tc = tid & 15;
    const int r0 = tr * 4, c0 = tc * 4;

    if (tc <= tr) {
        uint64_t acc2[4][2] = {{0ull,0ull},{0ull,0ull},{0ull,0ull},{0ull,0ull}};
        for (int n4 = 0; n4 < 128; n4 += 4) {
            float4 cr[4];
#pragma unroll
            for (int i = 0; i < 4; i++)
                cr[i] = *reinterpret_cast<const float4*>(Cs + (r0 + i) * CS_STR + n4);
#pragma unroll
            for (int nn = 0; nn < 4; nn++) {
                uint64_t b0 = *reinterpret_cast<const uint64_t*>(Bst + (n4 + nn) * TS_STR + c0);
                uint64_t b1 = *reinterpret_cast<const uint64_t*>(Bst + (n4 + nn) * TS_STR + c0 + 2);
#pragma unroll
                for (int i = 0; i < 4; i++) {
                    uint64_t a2 = dup2((&cr[i].x)[nn]);
                    FMA2(acc2[i][0], a2, b0);
                    FMA2(acc2[i][1], a2, b1);
                }
            }
        }
#pragma unroll
        for (int i = 0; i < 4; i++) {
            int l = r0 + i;
            float al = ac[l];
            float v0, v1, v2, v3;
            up2(acc2[i][0], v0, v1);
            up2(acc2[i][1], v2, v3);
            float4 o;
            o.x = (c0     <= l) ? v0 * expf(al - ac[c0])     : 0.f;
            o.y = (c0 + 1 <= l) ? v1 * expf(al - ac[c0 + 1]) : 0.f;
            o.z = (c0 + 2 <= l) ? v2 * expf(al - ac[c0 + 2]) : 0.f;
            o.w = (c0 + 3 <= l) ? v3 * expf(al - ac[c0 + 3]) : 0.f;
            *reinterpret_cast<float4*>(Gs + l * XS_STR + c0) = o;
        }
    }
    __syncthreads();

    {
        uint64_t acc2[4][2] = {{0ull,0ull},{0ull,0ull},{0ull,0ull},{0ull,0ull}};
        for (int s4 = 0; s4 < r0 + 4; s4 += 4) {
            float4 gr[4];
#pragma unroll
            for (int i = 0; i < 4; i++)
                gr[i] = *reinterpret_cast<const float4*>(Gs + (r0 + i) * XS_STR + s4);
#pragma unroll
            for (int ss = 0; ss < 4; ss++) {
                uint64_t x0 = *reinterpret_cast<const uint64_t*>(xs + (s4 + ss) * XS_STR + c0);
                uint64_t x1 = *reinterpret_cast<const uint64_t*>(xs + (s4 + ss) * XS_STR + c0 + 2);
#pragma unroll
                for (int i = 0; i < 4; i++) {
                    uint64_t a2 = dup2((&gr[i].x)[ss]);
                    FMA2(acc2[i][0], a2, x0);
                    FMA2(acc2[i][1], a2, x1);
                }
            }
        }
#pragma unroll
        for (int i = 0; i < 4; i++) {
            float v0, v1, v2, v3;
            up2(acc2[i][0], v0, v1);
            up2(acc2[i][1], v2, v3);
            *reinterpret_cast<float4*>(g_y + (size_t)(m0 + r0 + i) * DINNER + h * HD + c0) =
                make_float4(v0, v1, v2, v3);
        }
    }

    {
        const int p0 = (tid & 15) * 4, n0 = (tid >> 4) * 8;
        uint64_t acc2[2][8];
#pragma unroll
        for (int pp = 0; pp < 2; pp++)
#pragma unroll
            for (int j = 0; j < 8; j++) acc2[pp][j] = 0ull;
        for (int l = 0; l < 64; l++) {
            uint64_t w2 = dup2(wd[l]);
            uint64_t xa = *reinterpret_cast<const uint64_t*>(xs + l * XS_STR + p0);
            uint64_t xb = *reinterpret_cast<const uint64_t*>(xs + l * XS_STR + p0 + 2);
            uint64_t wxa, wxb;
            MUL2(wxa, xa, w2);
            MUL2(wxb, xb, w2);
#pragma unroll
            for (int j = 0; j < 8; j++) {
                uint64_t b2 = dup2(Bst[(n0 + j) * TS_STR + l]);
                FMA2(acc2[0][j], wxa, b2);
                FMA2(acc2[1][j], wxb, b2);
            }
        }
        float rowv[4][8];
#pragma unroll
        for (int pp = 0; pp < 2; pp++)
#pragma unroll
            for (int j = 0; j < 8; j++)
                up2(acc2[pp][j], rowv[2 * pp][j], rowv[2 * pp + 1][j]);
#pragma unroll
        for (int i = 0; i < 4; i++) {
            float* dst = g_states + ((size_t)blk * HD + p0 + i) * DSTATE + n0;
            *reinterpret_cast<float4*>(dst)     = make_float4(rowv[i][0], rowv[i][1], rowv[i][2], rowv[i][3]);
            *reinterpret_cast<float4*>(dst + 4) = make_float4(rowv[i][4], rowv[i][5], rowv[i][6], rowv[i][7]);
        }
    }
}

// ---------------- inter-chunk scan ----------------
__global__ void scan_kernel() {
    int idx = blockIdx.x * blockDim.x + threadIdx.x;
    int n = idx & 127;
    int p = (idx >> 7) & 63;
    int h = (idx >> 13) & 31;
    int b = idx >> 18;
    float prev = 0.f;
    for (int c = 0; c < NC; c++) {
        int bch = (b * NC + c) * NH + h;
        size_t off = ((size_t)bch * HD + p) * DSTATE + n;
        float loc = g_states[off];
        g_states[off] = prev;
        prev = fmaf(prev, g_suma[bch], loc);
    }
}

// ---------------- Y_off + skip (f32x2) ----------------
__global__ __launch_bounds__(256, 1) void yoff_kernel(const float* __restrict__ Dv) {
    int blk = blockIdx.x;
    int h = blk & 31;
    int c = (blk >> 5) & 63;
    int b = blk >> 11;
    int m0 = b * LSEQ + c * CHK;

    extern __shared__ float sm[];
    float* Pst = sm;
    float* Cs  = Pst + 128 * TS_STR;
    float* ac  = Cs + 64 * CS_STR;
    int tid = threadIdx.x;

    for (int i = tid; i < 64 * 128; i += 256) {
        int p = i >> 7, n = i & 127;
        Pst[n * TS_STR + p] = g_states[((size_t)blk * HD + p) * DSTATE + n];
    }
    for (int i = tid; i < 64 * 32; i += 256) {
        int l = i >> 5, q = i & 31;
        float4 v = *reinterpret_cast<const float4*>(
            g_xbc + (size_t)(m0 + l) * CONVCH + DINNER + DSTATE + 4 * q);
        *reinterpret_cast<float4*>(Cs + l * CS_STR + 4 * q) = v;
    }
    if (tid < 64) ac[tid] = g_acum[blk * CHK + tid];
    float Dh = Dv[h];
    __syncthreads();

    const int tr = tid >> 4, tc = tid & 15;
    const int r0 = tr * 4, c0 = tc * 4;
    uint64_t acc2[4][2] = {{0ull,0ull},{0ull,0ull},{0ull,0ull},{0ull,0ull}};
    for (int n4 = 0; n4 < 128; n4 += 4) {
        float4 cr[4];
#pragma unroll
        for (int i = 0; i < 4; i++)
            cr[i] = *reinterpret_cast<const float4*>(Cs + (r0 + i) * CS_STR + n4);
#pragma unroll
        for (int nn = 0; nn < 4; nn++) {
            uint64_t p0v = *reinterpret_cast<const uint64_t*>(Pst + (n4 + nn) * TS_STR + c0);
            uint64_t p1v = *reinterpret_cast<const uint64_t*>(Pst + (n4 + nn) * TS_STR + c0 + 2);
#pragma unroll
            for (int i = 0; i < 4; i++) {
                uint64_t a2 = dup2((&cr[i].x)[nn]);
                FMA2(acc2[i][0], a2, p0v);
                FMA2(acc2[i][1], a2, p1v);
            }
        }
    }
#pragma unroll
    for (int i = 0; i < 4; i++) {
        int l = r0 + i;
        int row = m0 + l;
        float el = expf(ac[l]);
        float v0, v1, v2, v3;
        up2(acc2[i][0], v0, v1);
        up2(acc2[i][1], v2, v3);
        float4 xv = *reinterpret_cast<const float4*>(
            g_xbc + (size_t)row * CONVCH + h * HD + c0);
        float4* yp = reinterpret_cast<float4*>(g_y + (size_t)row * DINNER + h * HD + c0);
        float4 yv = *yp;
        yv.x += v0 * el + xv.x * Dh;
        yv.y += v1 * el + xv.y * Dh;
        yv.z += v2 * el + xv.z * Dh;
        yv.w += v3 * el + xv.w * Dh;
        *yp = yv;
    }
}

// ---------------- gate (silu(z)) + RMSNorm, fused bf16 split output ----------------
__global__ void gate_kernel(const float* __restrict__ norm_w,
                            __nv_bfloat16* __restrict__ a2h, __nv_bfloat16* __restrict__ a2l) {
    int m = blockIdx.x;
    int tid = threadIdx.x;
    __shared__ float red[256];
    float tv[8];
    float ss = 0.f;
#pragma unroll
    for (int j = 0; j < 8; j++) {
        int i = tid + 256 * j;
        float zv = g_zx[(size_t)m * DPROJ + i];
        float yv = g_y[(size_t)m * DINNER + i];
        float g = yv * (zv / (1.f + expf(-zv)));
        tv[j] = g;
        ss += g * g;
    }
    red[tid] = ss;
    __syncthreads();
    for (int s = 128; s > 0; s >>= 1) {
        if (tid < s) red[tid] += red[tid + s];
        __syncthreads();
    }
    float scale = rsqrtf(red[0] / (float)DINNER + 1e-5f);
#pragma unroll
    for (int j = 0; j < 8; j++) {
        int i = tid + 256 * j;
        float val = tv[j] * scale * norm_w[i];
        __nv_bfloat16 hv = __float2bfloat16(val);
        a2h[(size_t)m * DINNER + i] = hv;
        a2l[(size_t)m * DINNER + i] = __float2bfloat16(val - __bfloat162float(hv));
    }
}

// ---------------- launch ----------------
extern "C" void kernel_launch(void* const* d_in, const int* in_sizes, int n_in,
                              void* d_out, int out_size) {
    const float* u      = (const float*)d_in[0];
    const float* W_in   = (const float*)d_in[1];
    const float* conv_w = (const float*)d_in[2];
    const float* conv_b = (const float*)d_in[3];
    const float* dt_b   = (const float*)d_in[4];
    const float* A_log  = (const float*)d_in[5];
    const float* Dv     = (const float*)d_in[6];
    const float* norm_w = (const float*)d_in[7];
    const float* W_out  = (const float*)d_in[8];
    float* out = (float*)d_out;

    float* zx = nullptr;
    cudaGetSymbolAddress((void**)&zx, g_zx);
    __nv_bfloat16 *a1h, *a1l, *b1h, *b1l, *a2h, *a2l, *b2h, *b2l;
    cudaGetSymbolAddress((void**)&a1h, g_a1h);
    cudaGetSymbolAddress((void**)&a1l, g_a1l);
    cudaGetSymbolAddress((void**)&b1h, g_b1h);
    cudaGetSymbolAddress((void**)&b1l, g_b1l);
    cudaGetSymbolAddress((void**)&a2h, g_a2h);
    cudaGetSymbolAddress((void**)&a2l, g_a2l);
    cudaGetSymbolAddress((void**)&b2h, g_b2h);
    cudaGetSymbolAddress((void**)&b2l, g_b2l);

    const size_t gemm_smem = 2 * 49152;   // 98304 -> 2 CTAs/SM
    const size_t diag_smem = (size_t)(128 * TS_STR + 64 * CS_STR + 2 * 64 * XS_STR + 128) * sizeof(float);
    const size_t yoff_smem = (size_t)(128 * TS_STR + 64 * CS_STR + 64) * sizeof(float);
    cudaFuncSetAttribute(hmma_gemm_kernel, cudaFuncAttributeMaxDynamicSharedMemorySize, (int)gemm_smem);
    cudaFuncSetAttribute(ssd_diag_kernel, cudaFuncAttributeMaxDynamicSharedMemorySize, (int)diag_smem);
    cudaFuncSetAttribute(yoff_kernel, cudaFuncAttributeMaxDynamicSharedMemorySize, (int)yoff_smem);

    // launches 0-2
    cvt_split_kernel<<<(MROWS * DMODEL / 4 + 255) / 256, 256>>>(u, a1h, a1l, MROWS * DMODEL / 4);
    transpose_split_kernel<<<dim3(NPAD1 / 32, DMODEL / 32), dim3(32, 32)>>>(W_in, b1h, b1l, DMODEL, DPROJ);
    transpose_split_kernel<<<dim3(DMODEL / 32, DINNER / 32), dim3(32, 32)>>>(W_out, b2h, b2l, DINNER, DMODEL);

    // launch 3 (ncu capture target): GEMM1 zx[8192,4384] = u @ W_in
    hmma_gemm_kernel<<<dim3(NPAD1 / 64, MROWS / 128), 256, gemm_smem>>>(
        a1h, a1l, b1h, b1l, zx, DPROJ, DMODEL, DPROJ);

    dt_kernel<<<MROWS * NH / 256, 256>>>(dt_b);
    acum_kernel<<<BQ * NC * NH / 256, 256>>>(A_log);
    conv_kernel<<<dim3(CONVCH / 256, MROWS / 16), 256>>>(conv_w, conv_b);
    ssd_diag_kernel<<<BQ * NC * NH, 256, diag_smem>>>();
    scan_kernel<<<(BQ * NH * HD * DSTATE) / 256, 256>>>();
    yoff_kernel<<<BQ * NC * NH, 256, yoff_smem>>>(Dv);
    gate_kernel<<<MROWS, 256>>>(norm_w, a2h, a2l);

    // GEMM2: out[8192,1024] = y @ W_out
    hmma_gemm_kernel<<<dim3(DMODEL / 64, MROWS / 128), 256, gemm_smem>>>(
        a2h, a2l, b2h, b2l, out, DMODEL, DINNER, DMODEL);
}